// round 3
// baseline (speedup 1.0000x reference)
#include <cuda_runtime.h>
#include <math.h>

#define B_ 64
#define H_ 1024

typedef unsigned long long ull;

// Scratch (allocation-free rule: __device__ globals)
__device__ float g_s[18][B_ * H_];  // partial pre-activations (split-K=2 per logical mat)
__device__ float g_ep[8][B_ * H_];  // split-K partials of e = k_t @ We

// packed f32x2 helpers (sm_103a FFMA2 path)
__device__ __forceinline__ ull pack2(float v) {
    ull d;
    unsigned r = __float_as_uint(v);
    asm("mov.b64 %0, {%1, %1};" : "=l"(d) : "r"(r));
    return d;
}
__device__ __forceinline__ void ffma2(ull& d, ull a, ull b) {
    asm("fma.rn.f32x2 %0, %1, %2, %0;" : "+l"(d) : "l"(a), "l"(b));
}

// ----------------------------------------------------------------------------
// Kernel 1: 18 partial GEMMs (9 logical mats x split-K 2), M=64, N=1024, K=512.
// CTA tile 64x128, 128 threads, 8x8 per-thread, packed fma.rn.f32x2.
// mats (lm = mat>>1, kh = mat&1):
//  lm: 0 x@Wi_x  1 h@Wi_h  2 x@Wf_x  3 h@Wf_h  4 x@Wo_x  5 h@Wo_h
//      6 x@Wk    7 x@Wv    8 h@Wq      each split into K halves kh*512.
// ----------------------------------------------------------------------------
__global__ __launch_bounds__(128, 1) void gemm18_kernel(
    const float* __restrict__ x, const float* __restrict__ h,
    const float* __restrict__ Wi, const float* __restrict__ Wf,
    const float* __restrict__ Wo, const float* __restrict__ Wk,
    const float* __restrict__ Wv, const float* __restrict__ Wq)
{
    constexpr int TK = 16;
    constexpr int NT = 512 / TK;  // 32 tiles
    __shared__ __align__(16) float As[2][TK][72];    // [k][m]
    __shared__ __align__(16) float Ws[2][TK][132];   // [k][n]

    const int mat = blockIdx.y;
    const int lm = mat >> 1;
    const int kh = mat & 1;
    const float* A;
    const float* W;
    switch (lm) {
        case 0: A = x; W = Wi;                      break;
        case 1: A = h; W = Wi + (size_t)H_ * H_;    break;
        case 2: A = x; W = Wf;                      break;
        case 3: A = h; W = Wf + (size_t)H_ * H_;    break;
        case 4: A = x; W = Wo;                      break;
        case 5: A = h; W = Wo + (size_t)H_ * H_;    break;
        case 6: A = x; W = Wk;                      break;
        case 7: A = x; W = Wv;                      break;
        default: A = h; W = Wq;                     break;
    }
    A += kh * 512;                    // column offset (row stride H_)
    W += (size_t)(kh * 512) * H_;     // row offset
    float* out = g_s[mat];

    const int n0 = blockIdx.x * 128;
    const int t  = threadIdx.x;
    const int trow = t >> 4;          // 0..7 -> rows trow*8..+7
    const int tcol = t & 15;          // cols n0+tcol*4..+3 and n0+64+tcol*4..+3

    // LDG mappings
    const int ar0 = t >> 2;           // 0..31 (and +32)
    const int akq = (t & 3) << 2;     // 0,4,8,12
    const int wr  = t >> 5;           // 0..3 (+4p)
    const int wc  = (t & 31) << 2;    // 0..124

    ull acc[8][4];
    #pragma unroll
    for (int i = 0; i < 8; i++)
        #pragma unroll
        for (int j = 0; j < 4; j++) acc[i][j] = 0ull;

    float4 pa0, pa1, pw[4];

    // prologue: tile 0 -> buffer 0
    pa0 = *(const float4*)(A + ar0 * H_ + akq);
    pa1 = *(const float4*)(A + (ar0 + 32) * H_ + akq);
    #pragma unroll
    for (int p = 0; p < 4; p++)
        pw[p] = *(const float4*)(W + (size_t)(wr + p * 4) * H_ + n0 + wc);
    As[0][akq + 0][ar0] = pa0.x;  As[0][akq + 1][ar0] = pa0.y;
    As[0][akq + 2][ar0] = pa0.z;  As[0][akq + 3][ar0] = pa0.w;
    As[0][akq + 0][ar0 + 32] = pa1.x;  As[0][akq + 1][ar0 + 32] = pa1.y;
    As[0][akq + 2][ar0 + 32] = pa1.z;  As[0][akq + 3][ar0 + 32] = pa1.w;
    #pragma unroll
    for (int p = 0; p < 4; p++)
        *(float4*)&Ws[0][wr + p * 4][wc] = pw[p];
    __syncthreads();

    #pragma unroll 1
    for (int tile = 0; tile < NT; tile++) {
        const int cur = tile & 1;
        const int nxt = cur ^ 1;

        if (tile + 1 < NT) {
            const int k0n = (tile + 1) * TK;
            pa0 = *(const float4*)(A + ar0 * H_ + k0n + akq);
            pa1 = *(const float4*)(A + (ar0 + 32) * H_ + k0n + akq);
            #pragma unroll
            for (int p = 0; p < 4; p++)
                pw[p] = *(const float4*)(W + (size_t)(k0n + wr + p * 4) * H_ + n0 + wc);
        }

        #pragma unroll
        for (int kk = 0; kk < TK; kk++) {
            float4 av0 = *(const float4*)&As[cur][kk][trow << 3];
            float4 av1 = *(const float4*)&As[cur][kk][(trow << 3) + 4];
            ulonglong2 bv0 = *(const ulonglong2*)&Ws[cur][kk][tcol << 2];
            ulonglong2 bv1 = *(const ulonglong2*)&Ws[cur][kk][64 + (tcol << 2)];

            ull pa[8];
            pa[0] = pack2(av0.x); pa[1] = pack2(av0.y);
            pa[2] = pack2(av0.z); pa[3] = pack2(av0.w);
            pa[4] = pack2(av1.x); pa[5] = pack2(av1.y);
            pa[6] = pack2(av1.z); pa[7] = pack2(av1.w);

            #pragma unroll
            for (int m = 0; m < 8; m++) {
                ffma2(acc[m][0], pa[m], bv0.x);
                ffma2(acc[m][1], pa[m], bv0.y);
                ffma2(acc[m][2], pa[m], bv1.x);
                ffma2(acc[m][3], pa[m], bv1.y);
            }
        }

        if (tile + 1 < NT) {
            As[nxt][akq + 0][ar0] = pa0.x;  As[nxt][akq + 1][ar0] = pa0.y;
            As[nxt][akq + 2][ar0] = pa0.z;  As[nxt][akq + 3][ar0] = pa0.w;
            As[nxt][akq + 0][ar0 + 32] = pa1.x;  As[nxt][akq + 1][ar0 + 32] = pa1.y;
            As[nxt][akq + 2][ar0 + 32] = pa1.z;  As[nxt][akq + 3][ar0 + 32] = pa1.w;
            #pragma unroll
            for (int p = 0; p < 4; p++)
                *(float4*)&Ws[nxt][wr + p * 4][wc] = pw[p];
        }
        __syncthreads();
    }

    #pragma unroll
    for (int m = 0; m < 8; m++) {
        const int row = (trow << 3) + m;
        float2 u0 = *(float2*)&acc[m][0];
        float2 u1 = *(float2*)&acc[m][1];
        float2 u2 = *(float2*)&acc[m][2];
        float2 u3 = *(float2*)&acc[m][3];
        *(float4*)(out + row * H_ + n0 + (tcol << 2)) =
            make_float4(u0.x, u0.y, u1.x, u1.y);
        *(float4*)(out + row * H_ + n0 + 64 + (tcol << 2)) =
            make_float4(u2.x, u2.y, u3.x, u3.y);
    }
}

// ----------------------------------------------------------------------------
// Kernel 2: e partials. A = (g_s[12]+g_s[13] + bk) [64,1024], W = We. split-K=8.
// grid (16 n-tiles, 8 k-chunks of 128). Double-buffered.
// ----------------------------------------------------------------------------
__global__ __launch_bounds__(256, 1) void egemm_kernel(
    const float* __restrict__ We, const float* __restrict__ bk)
{
    constexpr int TK = 32;
    __shared__ __align__(16) float As[2][TK][64 + 4];
    __shared__ __align__(16) float Ws[2][TK][64 + 4];

    const float* A0 = &g_s[12][0];
    const float* A1 = &g_s[13][0];
    float* out = &g_ep[blockIdx.y][0];
    const int kbase = blockIdx.y * 128;
    const int n0 = blockIdx.x * 64;
    const int t  = threadIdx.x;
    const int tr = t >> 4;
    const int tc = t & 15;

    const int arow = t >> 3;
    const int akq  = (t & 7) << 2;
    const int wr   = t >> 4;
    const int wc   = (t & 15) << 2;

    float acc[4][4] = {};
    float4 pa0, pa1, pc0, pc1, pw0, pw1, pb;

    // prologue: tile 0
    pa0 = *(const float4*)(A0 + arow * H_ + kbase + akq);
    pc0 = *(const float4*)(A1 + arow * H_ + kbase + akq);
    pa1 = *(const float4*)(A0 + (arow + 32) * H_ + kbase + akq);
    pc1 = *(const float4*)(A1 + (arow + 32) * H_ + kbase + akq);
    pb  = *(const float4*)(bk + kbase + akq);
    pw0 = *(const float4*)(We + (size_t)(kbase + wr) * H_ + n0 + wc);
    pw1 = *(const float4*)(We + (size_t)(kbase + wr + 16) * H_ + n0 + wc);
    As[0][akq + 0][arow] = pa0.x + pc0.x + pb.x;
    As[0][akq + 1][arow] = pa0.y + pc0.y + pb.y;
    As[0][akq + 2][arow] = pa0.z + pc0.z + pb.z;
    As[0][akq + 3][arow] = pa0.w + pc0.w + pb.w;
    As[0][akq + 0][arow + 32] = pa1.x + pc1.x + pb.x;
    As[0][akq + 1][arow + 32] = pa1.y + pc1.y + pb.y;
    As[0][akq + 2][arow + 32] = pa1.z + pc1.z + pb.z;
    As[0][akq + 3][arow + 32] = pa1.w + pc1.w + pb.w;
    *(float4*)&Ws[0][wr][wc]      = pw0;
    *(float4*)&Ws[0][wr + 16][wc] = pw1;
    __syncthreads();

    #pragma unroll 1
    for (int tile = 0; tile < 4; tile++) {
        const int cur = tile & 1;
        const int nxt = cur ^ 1;

        if (tile + 1 < 4) {
            const int k0n = kbase + (tile + 1) * TK;
            pa0 = *(const float4*)(A0 + arow * H_ + k0n + akq);
            pc0 = *(const float4*)(A1 + arow * H_ + k0n + akq);
            pa1 = *(const float4*)(A0 + (arow + 32) * H_ + k0n + akq);
            pc1 = *(const float4*)(A1 + (arow + 32) * H_ + k0n + akq);
            pb  = *(const float4*)(bk + k0n + akq);
            pw0 = *(const float4*)(We + (size_t)(k0n + wr) * H_ + n0 + wc);
            pw1 = *(const float4*)(We + (size_t)(k0n + wr + 16) * H_ + n0 + wc);
        }

        #pragma unroll
        for (int kk = 0; kk < TK; kk++) {
            float4 a = *(const float4*)&As[cur][kk][tr << 2];
            float4 b = *(const float4*)&Ws[cur][kk][tc << 2];
            #pragma unroll
            for (int i = 0; i < 4; i++) {
                float av = (i == 0) ? a.x : (i == 1) ? a.y : (i == 2) ? a.z : a.w;
                acc[i][0] = fmaf(av, b.x, acc[i][0]);
                acc[i][1] = fmaf(av, b.y, acc[i][1]);
                acc[i][2] = fmaf(av, b.z, acc[i][2]);
                acc[i][3] = fmaf(av, b.w, acc[i][3]);
            }
        }

        if (tile + 1 < 4) {
            As[nxt][akq + 0][arow] = pa0.x + pc0.x + pb.x;
            As[nxt][akq + 1][arow] = pa0.y + pc0.y + pb.y;
            As[nxt][akq + 2][arow] = pa0.z + pc0.z + pb.z;
            As[nxt][akq + 3][arow] = pa0.w + pc0.w + pb.w;
            As[nxt][akq + 0][arow + 32] = pa1.x + pc1.x + pb.x;
            As[nxt][akq + 1][arow + 32] = pa1.y + pc1.y + pb.y;
            As[nxt][akq + 2][arow + 32] = pa1.z + pc1.z + pb.z;
            As[nxt][akq + 3][arow + 32] = pa1.w + pc1.w + pb.w;
            *(float4*)&Ws[nxt][wr][wc]      = pw0;
            *(float4*)&Ws[nxt][wr + 16][wc] = pw1;
        }
        __syncthreads();
    }

    #pragma unroll
    for (int i = 0; i < 4; i++) {
        int row = (tr << 2) + i;
        float4 v = make_float4(acc[i][0], acc[i][1], acc[i][2], acc[i][3]);
        *(float4*)(out + row * H_ + n0 + (tc << 2)) = v;
    }
}

// ----------------------------------------------------------------------------
// Kernel 3: the roofline pass. Streams C_prev -> C_t once (streaming cache
// hints), fused with gates, h numerator dot, n_t, h_t. One warp per C row.
// ----------------------------------------------------------------------------
__device__ __forceinline__ float sigmoidf_(float z) {
    return 1.0f / (1.0f + expf(-z));
}

__global__ __launch_bounds__(256, 8) void update_kernel(
    const float* __restrict__ C_prev, const float* __restrict__ n_prev,
    const float* __restrict__ bi, const float* __restrict__ bf,
    const float* __restrict__ bo, const float* __restrict__ bk,
    const float* __restrict__ bv, const float* __restrict__ bq,
    const float* __restrict__ be,
    float* __restrict__ out_h, float* __restrict__ out_C,
    float* __restrict__ out_n)
{
    __shared__ __align__(16) float ks[H_];
    __shared__ __align__(16) float qs[H_];

    const int b    = blockIdx.y;
    const int r0   = blockIdx.x * 8;
    const int t    = threadIdx.x;
    const int w    = t >> 5;
    const int lane = t & 31;

    // k_t[b,:] and q_t[b,:] into smem (256 threads * float4 = 1024)
    {
        int c = t << 2;
        float4 k0 = *(const float4*)(&g_s[12][b * H_] + c);
        float4 k1 = *(const float4*)(&g_s[13][b * H_] + c);
        float4 bkv = *(const float4*)(bk + c);
        float4 q0 = *(const float4*)(&g_s[16][b * H_] + c);
        float4 q1 = *(const float4*)(&g_s[17][b * H_] + c);
        float4 bqv = *(const float4*)(bq + c);
        *(float4*)&ks[c] = make_float4(k0.x + k1.x + bkv.x, k0.y + k1.y + bkv.y,
                                       k0.z + k1.z + bkv.z, k0.w + k1.w + bkv.w);
        *(float4*)&qs[c] = make_float4(q0.x + q1.x + bqv.x, q0.y + q1.y + bqv.y,
                                       q0.z + q1.z + bqv.z, q0.w + q1.w + bqv.w);
    }
    __syncthreads();

    const int r = r0 + w;
    const int br = b * H_ + r;

    const float it = sigmoidf_(g_s[0][br] + g_s[1][br] + g_s[2][br] + g_s[3][br] + bi[r]);
    const float ft = sigmoidf_(g_s[4][br] + g_s[5][br] + g_s[6][br] + g_s[7][br] + bf[r]);
    const float ot = sigmoidf_(g_s[8][br] + g_s[9][br] + g_s[10][br] + g_s[11][br] + bo[r]);
    const float vt = g_s[14][br] + g_s[15][br] + bv[r];
    const float iv = it * vt;

    const size_t base = (size_t)b * H_ * H_ + (size_t)r * H_;
    float dot = 0.0f;

    #pragma unroll
    for (int it8 = 0; it8 < 8; it8++) {
        int c = (lane << 2) + (it8 << 7);
        float4 cp = __ldcs((const float4*)(C_prev + base + c));
        float4 kv = *(const float4*)&ks[c];
        float4 qv = *(const float4*)&qs[c];
        float4 ct;
        ct.x = fmaf(ft, cp.x, iv * kv.x);
        ct.y = fmaf(ft, cp.y, iv * kv.y);
        ct.z = fmaf(ft, cp.z, iv * kv.z);
        ct.w = fmaf(ft, cp.w, iv * kv.w);
        __stcs((float4*)(out_C + base + c), ct);
        dot = fmaf(ct.x, qv.x, dot);
        dot = fmaf(ct.y, qv.y, dot);
        dot = fmaf(ct.z, qv.z, dot);
        dot = fmaf(ct.w, qv.w, dot);
    }

    #pragma unroll
    for (int off = 16; off; off >>= 1)
        dot += __shfl_xor_sync(0xffffffffu, dot, off);

    if (lane == 0) {
        float e = be[r];
        #pragma unroll
        for (int p = 0; p < 8; p++) e += g_ep[p][br];
        float nt = fmaf(ft, n_prev[br], it * expf(e));
        out_n[br] = nt;
        out_h[br] = ot * dot / nt;
    }
}

// ----------------------------------------------------------------------------
extern "C" void kernel_launch(void* const* d_in, const int* in_sizes, int n_in,
                              void* d_out, int out_size)
{
    const float* x      = (const float*)d_in[0];
    const float* h_prev = (const float*)d_in[1];
    const float* C_prev = (const float*)d_in[2];
    const float* n_prev = (const float*)d_in[3];
    const float* Wi = (const float*)d_in[4];
    const float* bi = (const float*)d_in[5];
    const float* Wf = (const float*)d_in[6];
    const float* bf = (const float*)d_in[7];
    const float* Wo = (const float*)d_in[8];
    const float* bo = (const float*)d_in[9];
    const float* Wk = (const float*)d_in[10];
    const float* bk = (const float*)d_in[11];
    const float* Wv = (const float*)d_in[12];
    const float* bv = (const float*)d_in[13];
    const float* Wq = (const float*)d_in[14];
    const float* bq = (const float*)d_in[15];
    const float* We = (const float*)d_in[16];
    const float* be = (const float*)d_in[17];

    float* out_h = (float*)d_out;                          // [64, 1024]
    float* out_C = out_h + B_ * H_;                        // [64, 1024, 1024]
    float* out_n = out_C + (size_t)B_ * H_ * H_;           // [64, 1024]

    gemm18_kernel<<<dim3(8, 18), 128>>>(x, h_prev, Wi, Wf, Wo, Wk, Wv, Wq);
    egemm_kernel<<<dim3(16, 8), 256>>>(We, bk);
    update_kernel<<<dim3(128, 64), 256>>>(C_prev, n_prev, bi, bf, bo, bk, bv, bq, be,
                                          out_h, out_C, out_n);
}